// round 1
// baseline (speedup 1.0000x reference)
#include <cuda_runtime.h>
#include <math.h>

#define HEADS 12
#define DIM   64
#define BB    8
#define TT    1024
#define DIN   768
#define NPROJ (HEADS*DIM*2)   // 1536
#define NEGV  1000000000000.0f

// Scratch (static device allocations — no cudaMalloc allowed)
__device__ float g_q[BB*HEADS*TT*DIM];       // [b*H+h][t][d]
__device__ float g_k[BB*HEADS*TT*DIM];
__device__ float g_sin[TT*(DIM/2)];
__device__ float g_cos[TT*(DIM/2)];

// ---------------------------------------------------------------------------
// Kernel 0: RoPE table. Angle rounded to fp32 first (matches jnp fp32 ang),
// trig evaluated in double for accuracy.
// ---------------------------------------------------------------------------
__global__ void rope_table_kernel() {
    int id = blockIdx.x * blockDim.x + threadIdx.x;
    if (id >= TT * (DIM/2)) return;
    int t = id / (DIM/2);
    int i = id % (DIM/2);
    double invf = pow(10000.0, -(double)i / (double)(DIM/2));
    float ang = (float)((double)t * invf);
    double s, c;
    sincos((double)ang, &s, &c);
    g_sin[id] = (float)s;
    g_cos[id] = (float)c;
}

// ---------------------------------------------------------------------------
// Kernel 1: projection GEMM (M=8192, N=1536, K=768) + bias + RoPE epilogue.
// BM=128, BN=64, BK=16, 256 threads, 8x4 micro-tile per thread.
// ---------------------------------------------------------------------------
__global__ void proj_rope_kernel(const float* __restrict__ hs,
                                 const float* __restrict__ W,
                                 const float* __restrict__ bias) {
    __shared__ float As[16][132];   // [k][m], padded
    __shared__ float Bs[16][64];    // [k][n]

    const int tid = threadIdx.x;
    const int tx = tid & 15;        // n
    const int ty = tid >> 4;        // m
    const int m0 = blockIdx.y * 128;
    const int n0 = blockIdx.x * 64;

    float acc[8][4];
    #pragma unroll
    for (int r = 0; r < 8; r++)
        #pragma unroll
        for (int j = 0; j < 4; j++) acc[r][j] = 0.f;

    for (int k0 = 0; k0 < DIN; k0 += 16) {
        // A tile 128x16 -> transposed As[k][m]
        #pragma unroll
        for (int l = 0; l < 2; l++) {
            int f4  = tid + l * 256;          // 0..511
            int row = f4 >> 2;                // 0..127
            int kc  = (f4 & 3) * 4;
            float4 v = *reinterpret_cast<const float4*>(
                &hs[(size_t)(m0 + row) * DIN + k0 + kc]);
            As[kc+0][row] = v.x; As[kc+1][row] = v.y;
            As[kc+2][row] = v.z; As[kc+3][row] = v.w;
        }
        // B tile 16x64
        {
            int row = tid >> 4;               // 0..15
            int nc  = (tid & 15) * 4;
            *reinterpret_cast<float4*>(&Bs[row][nc]) =
                *reinterpret_cast<const float4*>(
                    &W[(size_t)(k0 + row) * NPROJ + n0 + nc]);
        }
        __syncthreads();

        #pragma unroll
        for (int kk = 0; kk < 16; kk++) {
            float4 a0 = *reinterpret_cast<const float4*>(&As[kk][ty*8]);
            float4 a1 = *reinterpret_cast<const float4*>(&As[kk][ty*8+4]);
            float4 bv = *reinterpret_cast<const float4*>(&Bs[kk][tx*4]);
            float a[8] = {a0.x,a0.y,a0.z,a0.w,a1.x,a1.y,a1.z,a1.w};
            float bb[4] = {bv.x,bv.y,bv.z,bv.w};
            #pragma unroll
            for (int r = 0; r < 8; r++)
                #pragma unroll
                for (int j = 0; j < 4; j++)
                    acc[r][j] = fmaf(a[r], bb[j], acc[r][j]);
        }
        __syncthreads();
    }

    // Epilogue: bias + RoPE, scatter into g_q / g_k.
    const int nbase = n0 + tx * 4;     // 4 consecutive cols, pair-aligned
    const int h     = nbase / 128;
    const int c0    = nbase % 128;
    const bool isk  = (c0 >= 64);
    const int dbase = c0 - (isk ? 64 : 0);
    float* dst = isk ? g_k : g_q;

    float bj[4];
    #pragma unroll
    for (int j = 0; j < 4; j++) bj[j] = bias[nbase + j];

    const int batch = m0 / TT;         // tile never crosses batch (1024%128==0)
    #pragma unroll
    for (int r = 0; r < 8; r++) {
        int m = m0 + ty * 8 + r;
        int t = m - batch * TT;
        #pragma unroll
        for (int p = 0; p < 2; p++) {
            int d = dbase + p * 2;
            int i = d >> 1;
            float s  = g_sin[t * 32 + i];
            float co = g_cos[t * 32 + i];
            float x0 = acc[r][p*2]   + bj[p*2];
            float x1 = acc[r][p*2+1] + bj[p*2+1];
            float o0 = x0 * co - x1 * s;
            float o1 = x1 * co + x0 * s;
            size_t off = ((size_t)(batch * HEADS + h) * TT + t) * DIM + d;
            *reinterpret_cast<float2*>(&dst[off]) = make_float2(o0, o1);
        }
    }
}

// ---------------------------------------------------------------------------
// Kernel 2: logits = (QK^T * m - (1-m)*NEG - tril_strict*NEG) / 8
// 64x64 tiles per (b,h). Tiles strictly below the diagonal: pure constant
// fill (logit vanishes in fp32 rounding against NEG — exact match).
// ---------------------------------------------------------------------------
__global__ void logits_kernel(const int* __restrict__ mask,
                              float* __restrict__ out) {
    const int tile_n = blockIdx.x;
    const int tile_m = blockIdx.y;
    const int bh     = blockIdx.z;
    const int b      = bh / HEADS;
    const int tid    = threadIdx.x;
    const size_t outbase = (size_t)bh * TT * TT;

    if (tile_n < tile_m) {
        // Entire tile strictly below diagonal: constant fill.
        #pragma unroll
        for (int l = 0; l < 4; l++) {
            int f4  = tid + l * 256;          // 0..1023
            int row = f4 >> 4;
            int c4  = (f4 & 15) * 4;
            int m = tile_m * 64 + row;
            int n = tile_n * 64 + c4;
            float4 v;
            float* vv = &v.x;
            #pragma unroll
            for (int j = 0; j < 4; j++) {
                float mv = (float)mask[b * TT + n + j];
                vv[j] = (-(1.0f - mv) * NEGV - NEGV) * 0.125f;
            }
            *reinterpret_cast<float4*>(&out[outbase + (size_t)m * TT + n]) = v;
        }
        return;
    }

    __shared__ float Qs[64][68];   // [d][t], padded (stride 272B, 16B-aligned)
    __shared__ float Ks[64][68];
    const float* qptr = g_q + (size_t)bh * TT * DIM;
    const float* kptr = g_k + (size_t)bh * TT * DIM;

    #pragma unroll
    for (int l = 0; l < 4; l++) {
        int f4  = tid + l * 256;
        int row = f4 >> 4;                 // local t
        int dg  = (f4 & 15) * 4;
        float4 q = *reinterpret_cast<const float4*>(
            &qptr[(size_t)(tile_m * 64 + row) * DIM + dg]);
        Qs[dg+0][row] = q.x; Qs[dg+1][row] = q.y;
        Qs[dg+2][row] = q.z; Qs[dg+3][row] = q.w;
        float4 kv = *reinterpret_cast<const float4*>(
            &kptr[(size_t)(tile_n * 64 + row) * DIM + dg]);
        Ks[dg+0][row] = kv.x; Ks[dg+1][row] = kv.y;
        Ks[dg+2][row] = kv.z; Ks[dg+3][row] = kv.w;
    }
    __syncthreads();

    const int tx = tid & 15;
    const int ty = tid >> 4;
    float acc[4][4] = {};
    #pragma unroll 16
    for (int kd = 0; kd < 64; kd++) {
        float4 q4 = *reinterpret_cast<const float4*>(&Qs[kd][ty*4]);
        float4 k4 = *reinterpret_cast<const float4*>(&Ks[kd][tx*4]);
        float qa[4] = {q4.x,q4.y,q4.z,q4.w};
        float ka[4] = {k4.x,k4.y,k4.z,k4.w};
        #pragma unroll
        for (int r = 0; r < 4; r++)
            #pragma unroll
            for (int j = 0; j < 4; j++)
                acc[r][j] = fmaf(qa[r], ka[j], acc[r][j]);
    }

    const int nb = tile_n * 64 + tx * 4;
    float mv[4];
    #pragma unroll
    for (int j = 0; j < 4; j++) mv[j] = (float)mask[b * TT + nb + j];

    #pragma unroll
    for (int r = 0; r < 4; r++) {
        int m = tile_m * 64 + ty * 4 + r;
        float4 v;
        float* vv = &v.x;
        #pragma unroll
        for (int j = 0; j < 4; j++) {
            float val = acc[r][j] * mv[j] - (1.0f - mv[j]) * NEGV;
            if (nb + j < m) val -= NEGV;    // strict lower triangle
            vv[j] = val * 0.125f;
        }
        *reinterpret_cast<float4*>(&out[outbase + (size_t)m * TT + nb]) = v;
    }
}

// ---------------------------------------------------------------------------
extern "C" void kernel_launch(void* const* d_in, const int* in_sizes, int n_in,
                              void* d_out, int out_size) {
    const float* hs   = (const float*)d_in[0];
    const int*   mask = (const int*)  d_in[1];
    const float* W    = (const float*)d_in[2];
    const float* bias = (const float*)d_in[3];
    float* out = (float*)d_out;

    rope_table_kernel<<<128, 256>>>();

    dim3 gA(NPROJ / 64, (BB * TT) / 128);   // (24, 64)
    proj_rope_kernel<<<gA, 256>>>(hs, W, bias);

    dim3 gB(TT / 64, TT / 64, BB * HEADS);  // (16, 16, 96)
    logits_kernel<<<gB, 256>>>(mask, out);
}

// round 2
// speedup vs baseline: 2.3642x; 2.3642x over previous
#include <cuda_runtime.h>
#include <cuda_bf16.h>
#include <math.h>

#define HEADS 12
#define DIM   64
#define BB    8
#define TT    1024
#define DIN   768
#define NPROJ 1536
#define NEGV  1000000000000.0f

// Scratch (no cudaMalloc allowed)
__device__ __nv_bfloat16 g_q[BB*HEADS*TT*DIM];   // [bh][t][d] bf16
__device__ __nv_bfloat16 g_k[BB*HEADS*TT*DIM];
__device__ float g_sin[TT*32];
__device__ float g_cos[TT*32];

// ---------------------------------------------------------------------------
__device__ __forceinline__ void mma16816(float d[4], const unsigned a[4],
                                         const unsigned b[2]) {
    asm volatile(
        "mma.sync.aligned.m16n8k16.row.col.f32.bf16.bf16.f32 "
        "{%0,%1,%2,%3}, {%4,%5,%6,%7}, {%8,%9}, {%0,%1,%2,%3};\n"
        : "+f"(d[0]), "+f"(d[1]), "+f"(d[2]), "+f"(d[3])
        : "r"(a[0]), "r"(a[1]), "r"(a[2]), "r"(a[3]), "r"(b[0]), "r"(b[1]));
}

// ---------------------------------------------------------------------------
// Kernel 0: RoPE table (double-precision trig, fp32-rounded angle like jnp).
// ---------------------------------------------------------------------------
__global__ void rope_table_kernel() {
    int id = blockIdx.x * blockDim.x + threadIdx.x;
    if (id >= TT * 32) return;
    int t = id >> 5;
    int i = id & 31;
    double invf = pow(10000.0, -(double)i / 32.0);
    float ang = (float)((double)t * invf);
    double s, c;
    sincos((double)ang, &s, &c);
    g_sin[id] = (float)s;
    g_cos[id] = (float)c;
}

// ---------------------------------------------------------------------------
// Kernel 1: projection GEMM (M=8192,N=1536,K=768) on bf16 tensor cores,
// bias + RoPE epilogue, Q/K scattered to bf16 scratch.
// Block 128x64, BK=32, 256 thr = 8 warps (4 M x 2 N), warp tile 32x32.
// ---------------------------------------------------------------------------
__global__ void __launch_bounds__(256)
proj_rope_kernel(const float* __restrict__ hs,
                 const float* __restrict__ W,
                 const float* __restrict__ bias) {
    // padded stride 40 bf16 = 20 words -> conflict-free fragment loads
    __shared__ __nv_bfloat16 As[128 * 40];   // [m][k]
    __shared__ __nv_bfloat16 Ws[64 * 40];    // [n][k] (transposed tile)

    const int tid  = threadIdx.x;
    const int m0   = blockIdx.y * 128;
    const int n0   = blockIdx.x * 64;
    const int warp = tid >> 5, lane = tid & 31;
    const int wm = warp >> 1, wn = warp & 1;
    const int g = lane >> 2, tig = lane & 3;

    unsigned* As32 = reinterpret_cast<unsigned*>(As);
    unsigned* Ws32 = reinterpret_cast<unsigned*>(Ws);

    float acc[2][4][4] = {};

    for (int k0 = 0; k0 < DIN; k0 += 32) {
        // A tile 128x32 fp32 -> bf16
        #pragma unroll
        for (int l = 0; l < 2; l++) {
            int f   = tid + l * 256;          // 0..511
            int row = f >> 2;
            int kc  = (f & 3) * 8;
            const float* src = &hs[(size_t)(m0 + row) * DIN + k0 + kc];
            float4 v0 = *reinterpret_cast<const float4*>(src);
            float4 v1 = *reinterpret_cast<const float4*>(src + 4);
            __nv_bfloat162* d2 =
                reinterpret_cast<__nv_bfloat162*>(&As[row * 40 + kc]);
            d2[0] = __floats2bfloat162_rn(v0.x, v0.y);
            d2[1] = __floats2bfloat162_rn(v0.z, v0.w);
            d2[2] = __floats2bfloat162_rn(v1.x, v1.y);
            d2[3] = __floats2bfloat162_rn(v1.z, v1.w);
        }
        // W tile 32x64 -> transposed [n][k]
        #pragma unroll
        for (int l = 0; l < 2; l++) {
            int f  = tid + l * 256;           // 0..511
            int kr = f >> 4;                  // 0..31
            int nc = (f & 15) * 4;
            float4 w = *reinterpret_cast<const float4*>(
                &W[(size_t)(k0 + kr) * NPROJ + n0 + nc]);
            Ws[(nc + 0) * 40 + kr] = __float2bfloat16(w.x);
            Ws[(nc + 1) * 40 + kr] = __float2bfloat16(w.y);
            Ws[(nc + 2) * 40 + kr] = __float2bfloat16(w.z);
            Ws[(nc + 3) * 40 + kr] = __float2bfloat16(w.w);
        }
        __syncthreads();

        #pragma unroll
        for (int ks2 = 0; ks2 < 16; ks2 += 8) {     // two k16 steps (word offs)
            unsigned a[2][4];
            #pragma unroll
            for (int mi = 0; mi < 2; mi++) {
                int r0 = wm * 32 + mi * 16 + g;
                a[mi][0] = As32[r0 * 20 + ks2 + tig];
                a[mi][1] = As32[(r0 + 8) * 20 + ks2 + tig];
                a[mi][2] = As32[r0 * 20 + ks2 + tig + 4];
                a[mi][3] = As32[(r0 + 8) * 20 + ks2 + tig + 4];
            }
            #pragma unroll
            for (int ni = 0; ni < 4; ni++) {
                int n = wn * 32 + ni * 8 + g;
                unsigned b[2];
                b[0] = Ws32[n * 20 + ks2 + tig];
                b[1] = Ws32[n * 20 + ks2 + tig + 4];
                mma16816(acc[0][ni], a[0], b);
                mma16816(acc[1][ni], a[1], b);
            }
        }
        __syncthreads();
    }

    // Epilogue: bias + RoPE, scatter bf16 pairs.
    #pragma unroll
    for (int ni = 0; ni < 4; ni++) {
        int n = n0 + wn * 32 + ni * 8 + 2 * tig;     // even
        float b0v = __ldg(&bias[n]);
        float b1v = __ldg(&bias[n + 1]);
        int h = n >> 7, c = n & 127;
        bool isk = (c >= 64);
        int dd = isk ? c - 64 : c;
        int ip = dd >> 1;
        __nv_bfloat16* dst = isk ? g_k : g_q;
        #pragma unroll
        for (int mi = 0; mi < 2; mi++) {
            #pragma unroll
            for (int rs = 0; rs < 2; rs++) {
                int m = m0 + wm * 32 + mi * 16 + g + rs * 8;
                int t = m & (TT - 1);
                int batch = m >> 10;
                float s  = g_sin[t * 32 + ip];
                float co = g_cos[t * 32 + ip];
                float x0 = acc[mi][ni][rs * 2 + 0] + b0v;
                float x1 = acc[mi][ni][rs * 2 + 1] + b1v;
                size_t off =
                    ((size_t)((batch * HEADS + h) * TT + t)) * DIM + dd;
                *reinterpret_cast<__nv_bfloat162*>(&dst[off]) =
                    __floats2bfloat162_rn(x0 * co - x1 * s, x1 * co + x0 * s);
            }
        }
    }
}

// ---------------------------------------------------------------------------
// Kernel 2: logits. 128x128 tiles per (b,h). Strict-lower tiles: constant
// fill (exact in fp32 vs NEG). Others: bf16 tensor-core QK^T.
// 256 thr = 8 warps (4 M x 2 N), warp tile 32x64.
// ---------------------------------------------------------------------------
__global__ void __launch_bounds__(256)
logits_kernel(const int* __restrict__ mask, float* __restrict__ out) {
    const int tile_n = blockIdx.x;
    const int tile_m = blockIdx.y;
    const int bh     = blockIdx.z;
    const int b      = bh / HEADS;
    const int tid    = threadIdx.x;
    const size_t outbase = (size_t)bh * TT * TT;

    if (tile_n < tile_m) {
        // Entire tile strictly below diagonal: constant fill.
        #pragma unroll
        for (int l = 0; l < 16; l++) {
            int f   = tid + l * 256;          // 0..4095 float4 tasks
            int row = f >> 5;
            int c4  = (f & 31) * 4;
            int m = tile_m * 128 + row;
            int n = tile_n * 128 + c4;
            float4 v;
            float* vv = &v.x;
            #pragma unroll
            for (int j = 0; j < 4; j++) {
                float mv = (float)mask[b * TT + n + j];
                vv[j] = (-(1.0f - mv) * NEGV - NEGV) * 0.125f;
            }
            *reinterpret_cast<float4*>(&out[outbase + (size_t)m * TT + n]) = v;
        }
        return;
    }

    // padded stride 72 bf16 = 36 words
    __shared__ __nv_bfloat16 Qs[128 * 72];
    __shared__ __nv_bfloat16 Ks[128 * 72];
    unsigned* Qs32 = reinterpret_cast<unsigned*>(Qs);
    unsigned* Ks32 = reinterpret_cast<unsigned*>(Ks);

    const __nv_bfloat16* qptr = g_q + (size_t)bh * TT * DIM +
                                (size_t)tile_m * 128 * DIM;
    const __nv_bfloat16* kptr = g_k + (size_t)bh * TT * DIM +
                                (size_t)tile_n * 128 * DIM;

    #pragma unroll
    for (int l = 0; l < 4; l++) {
        int f   = tid + l * 256;              // 0..1023 uint4 tasks
        int row = f >> 3;
        int qo  = (f & 7) * 8;                // bf16 offset, 16B aligned
        *reinterpret_cast<uint4*>(&Qs[row * 72 + qo]) =
            *reinterpret_cast<const uint4*>(&qptr[row * DIM + qo]);
        *reinterpret_cast<uint4*>(&Ks[row * 72 + qo]) =
            *reinterpret_cast<const uint4*>(&kptr[row * DIM + qo]);
    }
    __syncthreads();

    const int warp = tid >> 5, lane = tid & 31;
    const int wm = warp >> 1, wn = warp & 1;
    const int g = lane >> 2, tig = lane & 3;

    float acc[2][8][4] = {};
    #pragma unroll
    for (int ks2 = 0; ks2 < 32; ks2 += 8) {          // k = 0,16,32,48
        unsigned a[2][4];
        #pragma unroll
        for (int mi = 0; mi < 2; mi++) {
            int r0 = wm * 32 + mi * 16 + g;
            a[mi][0] = Qs32[r0 * 36 + ks2 + tig];
            a[mi][1] = Qs32[(r0 + 8) * 36 + ks2 + tig];
            a[mi][2] = Qs32[r0 * 36 + ks2 + tig + 4];
            a[mi][3] = Qs32[(r0 + 8) * 36 + ks2 + tig + 4];
        }
        #pragma unroll
        for (int ni = 0; ni < 8; ni++) {
            int n = wn * 64 + ni * 8 + g;
            unsigned bfr[2];
            bfr[0] = Ks32[n * 36 + ks2 + tig];
            bfr[1] = Ks32[n * 36 + ks2 + tig + 4];
            mma16816(acc[0][ni], a[0], bfr);
            mma16816(acc[1][ni], a[1], bfr);
        }
    }

    // Epilogue: mask, causal, scale, store.
    const int nb = tile_n * 128 + wn * 64;
    float mv0[8], mv1[8];
    #pragma unroll
    for (int ni = 0; ni < 8; ni++) {
        int n = nb + ni * 8 + 2 * tig;
        mv0[ni] = (float)mask[b * TT + n];
        mv1[ni] = (float)mask[b * TT + n + 1];
    }
    #pragma unroll
    for (int mi = 0; mi < 2; mi++) {
        #pragma unroll
        for (int rs = 0; rs < 2; rs++) {
            int m = tile_m * 128 + wm * 32 + mi * 16 + g + rs * 8;
            size_t rowoff = outbase + (size_t)m * TT;
            #pragma unroll
            for (int ni = 0; ni < 8; ni++) {
                int n = nb + ni * 8 + 2 * tig;
                float v0 = acc[mi][ni][rs * 2 + 0] * mv0[ni]
                           - (1.0f - mv0[ni]) * NEGV;
                float v1 = acc[mi][ni][rs * 2 + 1] * mv1[ni]
                           - (1.0f - mv1[ni]) * NEGV;
                if (n < m)     v0 -= NEGV;
                if (n + 1 < m) v1 -= NEGV;
                *reinterpret_cast<float2*>(&out[rowoff + n]) =
                    make_float2(v0 * 0.125f, v1 * 0.125f);
            }
        }
    }
}

// ---------------------------------------------------------------------------
extern "C" void kernel_launch(void* const* d_in, const int* in_sizes, int n_in,
                              void* d_out, int out_size) {
    const float* hs   = (const float*)d_in[0];
    const int*   mask = (const int*)  d_in[1];
    const float* W    = (const float*)d_in[2];
    const float* bias = (const float*)d_in[3];
    float* out = (float*)d_out;

    rope_table_kernel<<<128, 256>>>();

    dim3 gA(NPROJ / 64, (BB * TT) / 128);   // (24, 64)
    proj_rope_kernel<<<gA, 256>>>(hs, W, bias);

    dim3 gB(TT / 128, TT / 128, BB * HEADS);  // (8, 8, 96)
    logits_kernel<<<gB, 256>>>(mask, out);
}

// round 3
// speedup vs baseline: 3.3962x; 1.4366x over previous
#include <cuda_runtime.h>
#include <cuda_bf16.h>
#include <math.h>

#define HEADS 12
#define DIM   64
#define BB    8
#define TT    1024
#define DIN   768
#define NPROJ 1536
#define NEGV  1000000000000.0f

// Scratch (no cudaMalloc allowed)
__device__ __nv_bfloat16 g_hs[BB*TT*DIN];        // hidden_states bf16 [m][k]
__device__ __nv_bfloat16 g_wT[NPROJ*DIN];        // W transposed bf16 [n][k]
__device__ __nv_bfloat16 g_q[BB*HEADS*TT*DIM];   // [bh][t][d]
__device__ __nv_bfloat16 g_k[BB*HEADS*TT*DIM];
__device__ float g_sin[TT*32];
__device__ float g_cos[TT*32];

// ---------------------------------------------------------------------------
__device__ __forceinline__ void mma16816(float d[4], const unsigned a[4],
                                         const unsigned b[2]) {
    asm volatile(
        "mma.sync.aligned.m16n8k16.row.col.f32.bf16.bf16.f32 "
        "{%0,%1,%2,%3}, {%4,%5,%6,%7}, {%8,%9}, {%0,%1,%2,%3};\n"
        : "+f"(d[0]), "+f"(d[1]), "+f"(d[2]), "+f"(d[3])
        : "r"(a[0]), "r"(a[1]), "r"(a[2]), "r"(a[3]), "r"(b[0]), "r"(b[1]));
}

// ---------------------------------------------------------------------------
// Kernel 0: RoPE table, fp32 (bf16 noise downstream dwarfs sinf error).
// ---------------------------------------------------------------------------
__global__ void rope_table_kernel() {
    int id = blockIdx.x * blockDim.x + threadIdx.x;
    if (id >= TT * 32) return;
    int t = id >> 5;
    int i = id & 31;
    // log2(10000)/32
    float invf = exp2f(-(float)i * 0.4152410118610286f);
    float ang = (float)t * invf;
    float s, c;
    sincosf(ang, &s, &c);
    g_sin[id] = s;
    g_cos[id] = c;
}

// ---------------------------------------------------------------------------
// Kernel 1a: hs fp32 -> bf16 (contiguous).
// ---------------------------------------------------------------------------
__global__ void conv_hs_kernel(const float* __restrict__ hs) {
    int f = blockIdx.x * blockDim.x + threadIdx.x;   // float4 task
    float4 v = reinterpret_cast<const float4*>(hs)[f];
    __nv_bfloat162 lo = __floats2bfloat162_rn(v.x, v.y);
    __nv_bfloat162 hi = __floats2bfloat162_rn(v.z, v.w);
    uint2 o;
    o.x = *reinterpret_cast<unsigned*>(&lo);
    o.y = *reinterpret_cast<unsigned*>(&hi);
    reinterpret_cast<uint2*>(g_hs)[f] = o;
}

// ---------------------------------------------------------------------------
// Kernel 1b: W [768][1536] fp32 -> g_wT [1536][768] bf16 (tiled transpose).
// ---------------------------------------------------------------------------
__global__ void conv_w_kernel(const float* __restrict__ W) {
    __shared__ float tile[32][33];
    int n0 = blockIdx.x * 32, k0 = blockIdx.y * 32;
    int tx = threadIdx.x & 31, ty = threadIdx.x >> 5;   // 8 rows of workers
    #pragma unroll
    for (int r = ty; r < 32; r += 8)
        tile[r][tx] = W[(size_t)(k0 + r) * NPROJ + n0 + tx];
    __syncthreads();
    #pragma unroll
    for (int r = ty; r < 32; r += 8)
        g_wT[(size_t)(n0 + r) * DIN + k0 + tx] = __float2bfloat16(tile[tx][r]);
}

// ---------------------------------------------------------------------------
// Kernel 2: projection GEMM (M=8192,N=1536,K=768), bf16 operands from
// scratch, double-buffered smem, bias + RoPE epilogue -> g_q / g_k.
// Block 128x128, BK=32, 256 thr = 8 warps (4 M x 2 N), warp 32x64.
// ---------------------------------------------------------------------------
__global__ void __launch_bounds__(256, 2)
proj_rope_kernel(const float* __restrict__ bias) {
    __shared__ __nv_bfloat16 As[2][128 * 40];   // [m][k] stride 40
    __shared__ __nv_bfloat16 Bs[2][128 * 40];   // [n][k]

    const int tid  = threadIdx.x;
    const int m0   = blockIdx.y * 128;
    const int n0   = blockIdx.x * 128;
    const int warp = tid >> 5, lane = tid & 31;
    const int wm = warp >> 1, wn = warp & 1;
    const int g = lane >> 2, tig = lane & 3;

    // load task: f in 0..511 per operand -> row=f>>2, chunk=(f&3)*8 bf16
    const int r_row = tid >> 2;              // f = tid (+256)
    const int r_ch  = (tid & 3) * 8;

    float acc[2][8][4] = {};

    uint4 ra[2], rb[2];
    auto load_stage = [&](int k0) {
        #pragma unroll
        for (int l = 0; l < 2; l++) {
            int row = r_row + l * 64;
            ra[l] = *reinterpret_cast<const uint4*>(
                &g_hs[(size_t)(m0 + row) * DIN + k0 + r_ch]);
            rb[l] = *reinterpret_cast<const uint4*>(
                &g_wT[(size_t)(n0 + row) * DIN + k0 + r_ch]);
        }
    };
    auto store_stage = [&](int buf) {
        #pragma unroll
        for (int l = 0; l < 2; l++) {
            int row = r_row + l * 64;
            *reinterpret_cast<uint4*>(&As[buf][row * 40 + r_ch]) = ra[l];
            *reinterpret_cast<uint4*>(&Bs[buf][row * 40 + r_ch]) = rb[l];
        }
    };

    load_stage(0);
    store_stage(0);
    __syncthreads();

    int buf = 0;
    for (int kt = 0; kt < 24; kt++) {
        if (kt < 23) load_stage((kt + 1) * 32);

        const unsigned* As32 = reinterpret_cast<const unsigned*>(As[buf]);
        const unsigned* Bs32 = reinterpret_cast<const unsigned*>(Bs[buf]);
        #pragma unroll
        for (int ks2 = 0; ks2 < 16; ks2 += 8) {
            unsigned a[2][4];
            #pragma unroll
            for (int mi = 0; mi < 2; mi++) {
                int r0 = wm * 32 + mi * 16 + g;
                a[mi][0] = As32[r0 * 20 + ks2 + tig];
                a[mi][1] = As32[(r0 + 8) * 20 + ks2 + tig];
                a[mi][2] = As32[r0 * 20 + ks2 + tig + 4];
                a[mi][3] = As32[(r0 + 8) * 20 + ks2 + tig + 4];
            }
            #pragma unroll
            for (int ni = 0; ni < 8; ni++) {
                int n = wn * 64 + ni * 8 + g;
                unsigned b[2];
                b[0] = Bs32[n * 20 + ks2 + tig];
                b[1] = Bs32[n * 20 + ks2 + tig + 4];
                mma16816(acc[0][ni], a[0], b);
                mma16816(acc[1][ni], a[1], b);
            }
        }
        if (kt < 23) store_stage(buf ^ 1);
        __syncthreads();
        buf ^= 1;
    }

    // Epilogue: bias + RoPE, scatter bf16 pairs into g_q / g_k.
    #pragma unroll
    for (int ni = 0; ni < 8; ni++) {
        int n = n0 + wn * 64 + ni * 8 + 2 * tig;     // even column
        float b0v = __ldg(&bias[n]);
        float b1v = __ldg(&bias[n + 1]);
        int h = n >> 7, c = n & 127;
        bool isk = (c >= 64);
        int dd = isk ? c - 64 : c;
        int ip = dd >> 1;
        __nv_bfloat16* dst = isk ? g_k : g_q;
        #pragma unroll
        for (int mi = 0; mi < 2; mi++) {
            #pragma unroll
            for (int rs = 0; rs < 2; rs++) {
                int m = m0 + wm * 32 + mi * 16 + g + rs * 8;
                int t = m & (TT - 1);
                int batch = m >> 10;
                float s  = g_sin[t * 32 + ip];
                float co = g_cos[t * 32 + ip];
                float x0 = acc[mi][ni][rs * 2 + 0] + b0v;
                float x1 = acc[mi][ni][rs * 2 + 1] + b1v;
                size_t off =
                    ((size_t)((batch * HEADS + h) * TT + t)) * DIM + dd;
                *reinterpret_cast<__nv_bfloat162*>(&dst[off]) =
                    __floats2bfloat162_rn(x0 * co - x1 * s, x1 * co + x0 * s);
            }
        }
    }
}

// ---------------------------------------------------------------------------
// Kernel 3: logits compute — only upper-triangular 128x128 tiles (36/bh).
// ---------------------------------------------------------------------------
__global__ void __launch_bounds__(256)
logits_kernel(const int* __restrict__ mask, float* __restrict__ out) {
    // decode upper-tile index (tm <= tn), 36 tiles
    int idx = blockIdx.x;
    int tm = 0, rem = idx;
    while (rem >= 8 - tm) { rem -= 8 - tm; tm++; }
    const int tile_m = tm, tile_n = tm + rem;

    const int bh  = blockIdx.y;
    const int b   = bh / HEADS;
    const int tid = threadIdx.x;
    const size_t outbase = (size_t)bh * TT * TT;

    __shared__ __nv_bfloat16 Qs[128 * 72];
    __shared__ __nv_bfloat16 Ks[128 * 72];
    __shared__ float mvs[128];
    unsigned* Qs32 = reinterpret_cast<unsigned*>(Qs);
    unsigned* Ks32 = reinterpret_cast<unsigned*>(Ks);

    const __nv_bfloat16* qptr = g_q + (size_t)bh * TT * DIM +
                                (size_t)tile_m * 128 * DIM;
    const __nv_bfloat16* kptr = g_k + (size_t)bh * TT * DIM +
                                (size_t)tile_n * 128 * DIM;

    if (tid < 128) mvs[tid] = (float)mask[b * TT + tile_n * 128 + tid];

    #pragma unroll
    for (int l = 0; l < 4; l++) {
        int f   = tid + l * 256;
        int row = f >> 3;
        int qo  = (f & 7) * 8;
        *reinterpret_cast<uint4*>(&Qs[row * 72 + qo]) =
            *reinterpret_cast<const uint4*>(&qptr[row * DIM + qo]);
        *reinterpret_cast<uint4*>(&Ks[row * 72 + qo]) =
            *reinterpret_cast<const uint4*>(&kptr[row * DIM + qo]);
    }
    __syncthreads();

    const int warp = tid >> 5, lane = tid & 31;
    const int wm = warp >> 1, wn = warp & 1;
    const int g = lane >> 2, tig = lane & 3;

    float acc[2][8][4] = {};
    #pragma unroll
    for (int ks2 = 0; ks2 < 32; ks2 += 8) {
        unsigned a[2][4];
        #pragma unroll
        for (int mi = 0; mi < 2; mi++) {
            int r0 = wm * 32 + mi * 16 + g;
            a[mi][0] = Qs32[r0 * 36 + ks2 + tig];
            a[mi][1] = Qs32[(r0 + 8) * 36 + ks2 + tig];
            a[mi][2] = Qs32[r0 * 36 + ks2 + tig + 4];
            a[mi][3] = Qs32[(r0 + 8) * 36 + ks2 + tig + 4];
        }
        #pragma unroll
        for (int ni = 0; ni < 8; ni++) {
            int n = wn * 64 + ni * 8 + g;
            unsigned bfr[2];
            bfr[0] = Ks32[n * 36 + ks2 + tig];
            bfr[1] = Ks32[n * 36 + ks2 + tig + 4];
            mma16816(acc[0][ni], a[0], bfr);
            mma16816(acc[1][ni], a[1], bfr);
        }
    }

    const int nb = tile_n * 128 + wn * 64;
    const int nl = wn * 64 + 2 * tig;           // local col base in mvs
    float mv0[8], mv1[8];
    #pragma unroll
    for (int ni = 0; ni < 8; ni++) {
        mv0[ni] = mvs[nl + ni * 8];
        mv1[ni] = mvs[nl + ni * 8 + 1];
    }
    #pragma unroll
    for (int mi = 0; mi < 2; mi++) {
        #pragma unroll
        for (int rs = 0; rs < 2; rs++) {
            int m = tile_m * 128 + wm * 32 + mi * 16 + g + rs * 8;
            size_t rowoff = outbase + (size_t)m * TT;
            #pragma unroll
            for (int ni = 0; ni < 8; ni++) {
                int n = nb + wn * 0 + ni * 8 + 2 * tig + tile_n * 0;
                n = tile_n * 128 + nl + ni * 8;
                float v0 = acc[mi][ni][rs * 2 + 0] * mv0[ni]
                           - (1.0f - mv0[ni]) * NEGV;
                float v1 = acc[mi][ni][rs * 2 + 1] * mv1[ni]
                           - (1.0f - mv1[ni]) * NEGV;
                if (n < m)     v0 -= NEGV;
                if (n + 1 < m) v1 -= NEGV;
                *reinterpret_cast<float2*>(&out[rowoff + n]) =
                    make_float2(v0 * 0.125f, v1 * 0.125f);
            }
        }
    }
}

// ---------------------------------------------------------------------------
// Kernel 4: strict-lower fill — no big smem, per-column value staged once.
// Grid (28, 96): 28 strict-lower 128x128 tiles per bh.
// ---------------------------------------------------------------------------
__global__ void __launch_bounds__(256)
fill_kernel(const int* __restrict__ mask, float* __restrict__ out) {
    int idx = blockIdx.x;
    int tm = 1, rem = idx;
    while (rem >= tm) { rem -= tm; tm++; }
    const int tile_m = tm, tile_n = rem;

    const int bh  = blockIdx.y;
    const int b   = bh / HEADS;
    const int tid = threadIdx.x;
    const size_t outbase = (size_t)bh * TT * TT;

    __shared__ float colval[128];
    if (tid < 128) {
        float mv = (float)mask[b * TT + tile_n * 128 + tid];
        colval[tid] = (-(1.0f - mv) * NEGV - NEGV) * 0.125f;
    }
    __syncthreads();

    #pragma unroll
    for (int l = 0; l < 16; l++) {
        int f   = tid + l * 256;              // 0..4095 float4 tasks
        int row = f >> 5;
        int c4  = (f & 31) * 4;
        float4 v = *reinterpret_cast<const float4*>(&colval[c4]);
        int m = tile_m * 128 + row;
        int n = tile_n * 128 + c4;
        *reinterpret_cast<float4*>(&out[outbase + (size_t)m * TT + n]) = v;
    }
}

// ---------------------------------------------------------------------------
extern "C" void kernel_launch(void* const* d_in, const int* in_sizes, int n_in,
                              void* d_out, int out_size) {
    const float* hs   = (const float*)d_in[0];
    const int*   mask = (const int*)  d_in[1];
    const float* W    = (const float*)d_in[2];
    const float* bias = (const float*)d_in[3];
    float* out = (float*)d_out;

    rope_table_kernel<<<128, 256>>>();
    conv_hs_kernel<<<(BB*TT*DIN/4 + 255)/256, 256>>>(hs);
    conv_w_kernel<<<dim3(NPROJ/32, DIN/32), 256>>>(W);

    dim3 gA(NPROJ / 128, (BB * TT) / 128);   // (12, 64)
    proj_rope_kernel<<<gA, 256>>>(bias);

    dim3 gB(36, BB * HEADS);                 // upper tiles
    logits_kernel<<<gB, 256>>>(mask, out);

    dim3 gC(28, BB * HEADS);                 // strict-lower tiles
    fill_kernel<<<gC, 256>>>(mask, out);
}